// round 1
// baseline (speedup 1.0000x reference)
#include <cuda_runtime.h>
#include <math.h>

#define BB 8
#define NN 2048
#define DD 1024

// Scratch (allocation-free rule: __device__ globals)
__device__ float g_u[BB * NN * DD];   // field_in -> normalized pair vectors (64 MB)
__device__ float g_v[BB * NN * DD];   // values (64 MB)
__device__ float g_c[BB * NN * NN];   // coupling (128 MB)

#define BM 128
#define BN 128
#define BK 8
#define TM 8
#define TN 8
// 256 threads = 16x16 thread tile, each thread owns 8x8 outputs

// EPI: 0 = plain store, 1 = row-scale (gates), 2 = resonance update (clip(lam*racc + s*acc))
template <int EPI, bool TRANSB>
__global__ __launch_bounds__(256) void sgemm_kernel(
    const float* __restrict__ Ag, const float* __restrict__ Bg,
    float* __restrict__ Cg, int M, int N, int K,
    long long sA, long long sB, long long sC,
    const float* __restrict__ rowScale,  // EPI==1
    const float* __restrict__ raccIn,    // EPI==2
    float resScale)                      // EPI==2: (1-LAM)/pairs
{
    int b = blockIdx.z;
    const float* A  = Ag + (long long)b * sA;
    const float* Bm = Bg + (long long)b * sB;
    float* C        = Cg + (long long)b * sC;
    const float* racc = (EPI == 2) ? (raccIn + (long long)b * sC) : nullptr;

    __shared__ float As[BK][BM];
    __shared__ float Bs[BK][BN];

    int tid = threadIdx.x;
    int tx = tid & 15;
    int ty = tid >> 4;
    int rowBlock = blockIdx.y * BM;
    int colBlock = blockIdx.x * BN;

    // A tile loader: BM x BK, float4 along K
    int aRow = tid >> 1;
    int aCol = (tid & 1) * 4;
    // B tile loader
    int bRow, bCol;
    if (TRANSB) { bRow = tid >> 1; bCol = (tid & 1) * 4; }   // BN x BK (K-contig)
    else        { bRow = tid >> 5; bCol = (tid & 31) * 4; }  // BK x BN (N-contig)

    float acc[TM][TN];
#pragma unroll
    for (int i = 0; i < TM; i++)
#pragma unroll
        for (int j = 0; j < TN; j++) acc[i][j] = 0.0f;

    const float* Aptr = A + (long long)(rowBlock + aRow) * K + aCol;
    const float* Bptr = TRANSB ? (Bm + (long long)(colBlock + bRow) * K + bCol)
                               : (Bm + (long long)bRow * N + colBlock + bCol);

    for (int k0 = 0; k0 < K; k0 += BK) {
        float4 av = *(const float4*)(Aptr + k0);
        As[aCol + 0][aRow] = av.x;
        As[aCol + 1][aRow] = av.y;
        As[aCol + 2][aRow] = av.z;
        As[aCol + 3][aRow] = av.w;
        if (TRANSB) {
            float4 bv = *(const float4*)(Bptr + k0);
            Bs[bCol + 0][bRow] = bv.x;
            Bs[bCol + 1][bRow] = bv.y;
            Bs[bCol + 2][bRow] = bv.z;
            Bs[bCol + 3][bRow] = bv.w;
        } else {
            float4 bv = *(const float4*)(Bptr + (long long)k0 * N);
            *(float4*)&Bs[bRow][bCol] = bv;
        }
        __syncthreads();

#pragma unroll
        for (int kk = 0; kk < BK; kk++) {
            float ar[TM], br[TN];
#pragma unroll
            for (int i = 0; i < TM; i++) ar[i] = As[kk][ty * TM + i];
#pragma unroll
            for (int j = 0; j < TN; j++) br[j] = Bs[kk][tx * TN + j];
#pragma unroll
            for (int i = 0; i < TM; i++)
#pragma unroll
                for (int j = 0; j < TN; j++) acc[i][j] += ar[i] * br[j];
        }
        __syncthreads();
    }

    // Epilogue
#pragma unroll
    for (int i = 0; i < TM; i++) {
        int r = rowBlock + ty * TM + i;
        long long off = (long long)r * N + colBlock + tx * TN;
        float rs = 1.0f;
        if (EPI == 1) rs = rowScale[r];
#pragma unroll
        for (int j4 = 0; j4 < TN; j4 += 4) {
            float4 ov;
            if (EPI == 2) {
                float4 rv = *(const float4*)(racc + off + j4);
                ov.x = fminf(fmaxf(0.7f * rv.x + resScale * acc[i][j4 + 0], -2.0f), 2.0f);
                ov.y = fminf(fmaxf(0.7f * rv.y + resScale * acc[i][j4 + 1], -2.0f), 2.0f);
                ov.z = fminf(fmaxf(0.7f * rv.z + resScale * acc[i][j4 + 2], -2.0f), 2.0f);
                ov.w = fminf(fmaxf(0.7f * rv.w + resScale * acc[i][j4 + 3], -2.0f), 2.0f);
            } else {
                ov.x = acc[i][j4 + 0] * rs;
                ov.y = acc[i][j4 + 1] * rs;
                ov.z = acc[i][j4 + 2] * rs;
                ov.w = acc[i][j4 + 3] * rs;
            }
            *(float4*)(C + off + j4) = ov;
        }
    }
}

// cos(atan2(y+e, x+e)) = (x+e)/r, sin = (y+e)/r  -> normalize each 2-vector in place
__global__ void pairnorm_kernel(float* __restrict__ a, long long nPairs) {
    long long i = (long long)blockIdx.x * blockDim.x + threadIdx.x;
    if (i >= nPairs) return;
    float2 v = ((const float2*)a)[i];
    float x = v.x + 1e-8f;
    float y = v.y + 1e-8f;
    float inv = rsqrtf(x * x + y * y);
    ((float2*)a)[i] = make_float2(x * inv, y * inv);
}

// One block per (b, n) row: sigmoid, gates, zero diag, row-normalize
__global__ __launch_bounds__(256) void coupling_kernel(
    const float* __restrict__ raccNew, const float* __restrict__ gates,
    const float* __restrict__ condPtr, float* __restrict__ coupling)
{
    int n = blockIdx.x;
    int b = blockIdx.y;
    const float* row = raccNew + ((long long)b * NN + n) * NN;
    float* out       = coupling + ((long long)b * NN + n) * NN;
    float cond = fminf(fmaxf(condPtr[0], -5.0f), 5.0f);
    float gn = gates[b * NN + n];

    int t = threadIdx.x;  // 256 threads, 8 elements each
    float local[NN / 256];
    float sum = 0.0f;
#pragma unroll
    for (int it = 0; it < NN / 256; it++) {
        int m = t + it * 256;
        float v = row[m];
        float s = 1.0f / (1.0f + expf(-cond * v));
        float c = s * gates[b * NN + m] * gn;
        if (m == n) c = 0.0f;
        local[it] = c;
        sum += c;
    }
    __shared__ float red[256];
    red[t] = sum;
    __syncthreads();
    for (int s = 128; s > 0; s >>= 1) {
        if (t < s) red[t] += red[t + s];
        __syncthreads();
    }
    float inv = 1.0f / (red[0] + 1e-8f);
#pragma unroll
    for (int it = 0; it < NN / 256; it++) out[t + it * 256] = local[it] * inv;
}

extern "C" void kernel_launch(void* const* d_in, const int* in_sizes, int n_in,
                              void* d_out, int out_size) {
    const float* S    = (const float*)d_in[0];  // node_states (B,N,D)
    const float* G    = (const float*)d_in[1];  // node_gates  (B,N,1)
    const float* Racc = (const float*)d_in[2];  // r_acc       (B,N,N)
    const float* Win  = (const float*)d_in[3];  // W_in        (D,D)
    const float* Wout = (const float*)d_in[4];  // W_out       (D,D)
    const float* cond = (const float*)d_in[5];  // conductance scalar

    float* field = (float*)d_out;                       // (B,N,D)
    float* raccO = field + (size_t)BB * NN * DD;        // (B,N,N)

    float *u, *v, *c;
    cudaGetSymbolAddress((void**)&u, g_u);
    cudaGetSymbolAddress((void**)&v, g_v);
    cudaGetSymbolAddress((void**)&c, g_c);

    const int M1 = BB * NN;  // 16384

    // 1. a = S @ Win^T   (M1 x D x D)
    sgemm_kernel<0, true><<<dim3(DD / BN, M1 / BM, 1), 256>>>(
        S, Win, u, M1, DD, DD, 0, 0, 0, nullptr, nullptr, 0.0f);

    // 2. normalize pairs in place  (u becomes [cos|sin] interleaved)
    long long np = (long long)BB * NN * (DD / 2);
    pairnorm_kernel<<<(int)((np + 255) / 256), 256>>>(u, np);

    // 3. racc_new = clip(0.7*racc + (0.3/pairs) * U U^T, -2, 2)  (batched NT)
    sgemm_kernel<2, true><<<dim3(NN / BN, NN / BM, BB), 256>>>(
        u, u, raccO, NN, NN, DD,
        (long long)NN * DD, (long long)NN * DD, (long long)NN * NN,
        nullptr, Racc, 0.3f / (float)(DD / 2));

    // 4. coupling rows (sigmoid, gates, zero-diag, normalize)
    coupling_kernel<<<dim3(NN, BB), 256>>>(raccO, G, cond, c);

    // 5. values = (S * g) @ Wout^T  — gate folded in as epilogue row-scale
    sgemm_kernel<1, true><<<dim3(DD / BN, M1 / BM, 1), 256>>>(
        S, Wout, v, M1, DD, DD, 0, 0, 0, G, nullptr, 0.0f);

    // 6. field = coupling @ values  (batched NN)
    sgemm_kernel<0, false><<<dim3(DD / BN, NN / BM, BB), 256>>>(
        c, v, field, NN, DD, NN,
        (long long)NN * NN, (long long)NN * DD, (long long)NN * DD,
        nullptr, nullptr, 0.0f);
}

// round 2
// speedup vs baseline: 1.2466x; 1.2466x over previous
#include <cuda_runtime.h>
#include <math.h>
#include <stdint.h>

#define BB 8
#define NN 2048
#define DD 1024

// Scratch (allocation-free rule: __device__ globals)
__device__ float g_u[BB * NN * DD];   // field_in -> normalized pair vectors (64 MB)
__device__ float g_v[BB * NN * DD];   // values (64 MB)
__device__ float g_c[BB * NN * NN];   // coupling (128 MB)

__device__ __forceinline__ uint32_t f2tf(float x) {
    uint32_t r;
    asm("cvt.rna.tf32.f32 %0, %1;" : "=r"(r) : "f"(x));
    return r;
}

__device__ __forceinline__ void mma8(float* c,
    uint32_t a0, uint32_t a1, uint32_t a2, uint32_t a3,
    uint32_t b0, uint32_t b1)
{
    asm volatile(
        "mma.sync.aligned.m16n8k8.row.col.f32.tf32.tf32.f32 "
        "{%0,%1,%2,%3}, {%4,%5,%6,%7}, {%8,%9}, {%0,%1,%2,%3};"
        : "+f"(c[0]), "+f"(c[1]), "+f"(c[2]), "+f"(c[3])
        : "r"(a0), "r"(a1), "r"(a2), "r"(a3), "r"(b0), "r"(b1));
}

// 128x128 block tile, BK=16, 8 warps (2x4), warp tile 64x32 of m16n8k8 MMAs.
// EPI: 0 plain, 1 row-scale (gates), 2 resonance clip-lerp epilogue.
// TRANSB: B stored [N,K] (true) vs [K,N] (false).
// CORR: TF32x3 error-corrected (split hi/lo, 3 MMAs per tile).
template <int EPI, bool TRANSB, bool CORR>
__global__ __launch_bounds__(256, 1) void tgemm(
    const float* __restrict__ Ag, const float* __restrict__ Bg,
    float* __restrict__ Cg, int M, int N, int K,
    long long sA, long long sB, long long sC,
    const float* __restrict__ rowScale,
    const float* __restrict__ raccIn, float resScale)
{
    const int b = blockIdx.z;
    const float* A  = Ag + (long long)b * sA;
    const float* Bm = Bg + (long long)b * sB;
    float* C        = Cg + (long long)b * sC;
    const float* racc = (EPI == 2) ? (raccIn + (long long)b * sC) : nullptr;

    __shared__ uint32_t Ah[16][132];
    __shared__ uint32_t Bh[16][132];
    __shared__ uint32_t Al[CORR ? 16 : 1][CORR ? 132 : 4];
    __shared__ uint32_t Bl[CORR ? 16 : 1][CORR ? 132 : 4];

    const int tid  = threadIdx.x;
    const int lane = tid & 31;
    const int warp = tid >> 5;
    const int wm = (warp >> 2) * 64;   // warp row offset in block tile
    const int wn = (warp & 3) * 32;    // warp col offset
    const int rowBlock = blockIdx.y * 128;
    const int colBlock = blockIdx.x * 128;

    float acc[4][4][4];
#pragma unroll
    for (int i = 0; i < 4; i++)
#pragma unroll
        for (int j = 0; j < 4; j++)
#pragma unroll
            for (int r = 0; r < 4; r++) acc[i][j][r] = 0.0f;

    const int kq = lane & 3;   // k quad
    const int mq = lane >> 2;  // row-in-group

    for (int k0 = 0; k0 < K; k0 += 16) {
        // ---- load A tile (128 x 16), transpose into Ah[k][m] as tf32 ----
#pragma unroll
        for (int h = 0; h < 2; h++) {
            int f = tid + h * 256;
            int row = f >> 2, c4 = (f & 3) * 4;
            float4 v = *(const float4*)(A + (long long)(rowBlock + row) * K + k0 + c4);
            float vv[4] = {v.x, v.y, v.z, v.w};
#pragma unroll
            for (int c = 0; c < 4; c++) {
                uint32_t hi = f2tf(vv[c]);
                Ah[c4 + c][row] = hi;
                if (CORR) Al[c4 + c][row] = f2tf(vv[c] - __uint_as_float(hi));
            }
        }
        // ---- load B tile into Bh[k][n] ----
        if (TRANSB) {
#pragma unroll
            for (int h = 0; h < 2; h++) {
                int f = tid + h * 256;
                int row = f >> 2, c4 = (f & 3) * 4;  // row = n index, c4 = k
                float4 v = *(const float4*)(Bm + (long long)(colBlock + row) * K + k0 + c4);
                float vv[4] = {v.x, v.y, v.z, v.w};
#pragma unroll
                for (int c = 0; c < 4; c++) {
                    uint32_t hi = f2tf(vv[c]);
                    Bh[c4 + c][row] = hi;
                    if (CORR) Bl[c4 + c][row] = f2tf(vv[c] - __uint_as_float(hi));
                }
            }
        } else {
#pragma unroll
            for (int h = 0; h < 2; h++) {
                int f = tid + h * 256;
                int kr = f >> 5, c4 = (f & 31) * 4;  // kr = k index, c4 = n
                float4 v = *(const float4*)(Bm + (long long)(k0 + kr) * N + colBlock + c4);
                float vv[4] = {v.x, v.y, v.z, v.w};
#pragma unroll
                for (int c = 0; c < 4; c++) {
                    uint32_t hi = f2tf(vv[c]);
                    Bh[kr][c4 + c] = hi;
                    if (CORR) Bl[kr][c4 + c] = f2tf(vv[c] - __uint_as_float(hi));
                }
            }
        }
        __syncthreads();

        // ---- 2 k-sub-steps of 8 ----
#pragma unroll
        for (int ks = 0; ks < 2; ks++) {
            const int kb = ks * 8;
            uint32_t ah[4][4], bh[4][2];
            uint32_t al[4][4], bl[4][2];
#pragma unroll
            for (int i = 0; i < 4; i++) {
                int mB = wm + i * 16 + mq;
                ah[i][0] = Ah[kb + kq][mB];
                ah[i][1] = Ah[kb + kq][mB + 8];
                ah[i][2] = Ah[kb + kq + 4][mB];
                ah[i][3] = Ah[kb + kq + 4][mB + 8];
                if (CORR) {
                    al[i][0] = Al[kb + kq][mB];
                    al[i][1] = Al[kb + kq][mB + 8];
                    al[i][2] = Al[kb + kq + 4][mB];
                    al[i][3] = Al[kb + kq + 4][mB + 8];
                }
            }
#pragma unroll
            for (int j = 0; j < 4; j++) {
                int nB = wn + j * 8 + mq;
                bh[j][0] = Bh[kb + kq][nB];
                bh[j][1] = Bh[kb + kq + 4][nB];
                if (CORR) {
                    bl[j][0] = Bl[kb + kq][nB];
                    bl[j][1] = Bl[kb + kq + 4][nB];
                }
            }
#pragma unroll
            for (int i = 0; i < 4; i++)
#pragma unroll
                for (int j = 0; j < 4; j++) {
                    mma8(acc[i][j], ah[i][0], ah[i][1], ah[i][2], ah[i][3],
                         bh[j][0], bh[j][1]);
                    if (CORR) {
                        mma8(acc[i][j], ah[i][0], ah[i][1], ah[i][2], ah[i][3],
                             bl[j][0], bl[j][1]);
                        mma8(acc[i][j], al[i][0], al[i][1], al[i][2], al[i][3],
                             bh[j][0], bh[j][1]);
                    }
                }
        }
        __syncthreads();
    }

    // ---- epilogue: scattered float2 stores ----
#pragma unroll
    for (int i = 0; i < 4; i++) {
        int r0 = rowBlock + wm + i * 16 + (lane >> 2);
#pragma unroll
        for (int j = 0; j < 4; j++) {
            int c0 = colBlock + wn + j * 8 + (lane & 3) * 2;
#pragma unroll
            for (int h = 0; h < 2; h++) {
                int rr = r0 + h * 8;
                float x = acc[i][j][h * 2 + 0];
                float y = acc[i][j][h * 2 + 1];
                long long off = (long long)rr * N + c0;
                if (EPI == 1) { float rs = rowScale[rr]; x *= rs; y *= rs; }
                if (EPI == 2) {
                    float2 rv = *(const float2*)(racc + off);
                    x = fminf(fmaxf(0.7f * rv.x + resScale * x, -2.0f), 2.0f);
                    y = fminf(fmaxf(0.7f * rv.y + resScale * y, -2.0f), 2.0f);
                }
                *(float2*)(C + off) = make_float2(x, y);
            }
        }
    }
}

// cos(atan2(y+e, x+e)) = (x+e)/r, sin = (y+e)/r  -> normalize each 2-vector in place
__global__ void pairnorm_kernel(float* __restrict__ a, long long nPairs) {
    long long i = (long long)blockIdx.x * blockDim.x + threadIdx.x;
    if (i >= nPairs) return;
    float2 v = ((const float2*)a)[i];
    float x = v.x + 1e-8f;
    float y = v.y + 1e-8f;
    float inv = rsqrtf(x * x + y * y);
    ((float2*)a)[i] = make_float2(x * inv, y * inv);
}

// One block per (b, n) row: sigmoid, gates, zero diag, row-normalize
__global__ __launch_bounds__(256) void coupling_kernel(
    const float* __restrict__ raccNew, const float* __restrict__ gates,
    const float* __restrict__ condPtr, float* __restrict__ coupling)
{
    int n = blockIdx.x;
    int b = blockIdx.y;
    const float* row = raccNew + ((long long)b * NN + n) * NN;
    float* out       = coupling + ((long long)b * NN + n) * NN;
    float cond = fminf(fmaxf(condPtr[0], -5.0f), 5.0f);
    float gn = gates[b * NN + n];

    int t = threadIdx.x;
    float local[NN / 256];
    float sum = 0.0f;
#pragma unroll
    for (int it = 0; it < NN / 256; it++) {
        int m = t + it * 256;
        float v = row[m];
        float s = 1.0f / (1.0f + expf(-cond * v));
        float c = s * gates[b * NN + m] * gn;
        if (m == n) c = 0.0f;
        local[it] = c;
        sum += c;
    }
    __shared__ float red[256];
    red[t] = sum;
    __syncthreads();
    for (int s = 128; s > 0; s >>= 1) {
        if (t < s) red[t] += red[t + s];
        __syncthreads();
    }
    float inv = 1.0f / (red[0] + 1e-8f);
#pragma unroll
    for (int it = 0; it < NN / 256; it++) out[t + it * 256] = local[it] * inv;
}

extern "C" void kernel_launch(void* const* d_in, const int* in_sizes, int n_in,
                              void* d_out, int out_size) {
    const float* S    = (const float*)d_in[0];  // node_states (B,N,D)
    const float* G    = (const float*)d_in[1];  // node_gates  (B,N,1)
    const float* Racc = (const float*)d_in[2];  // r_acc       (B,N,N)
    const float* Win  = (const float*)d_in[3];  // W_in        (D,D)
    const float* Wout = (const float*)d_in[4];  // W_out       (D,D)
    const float* cond = (const float*)d_in[5];  // conductance scalar

    float* field = (float*)d_out;                       // (B,N,D)
    float* raccO = field + (size_t)BB * NN * DD;        // (B,N,N)

    float *u, *v, *c;
    cudaGetSymbolAddress((void**)&u, g_u);
    cudaGetSymbolAddress((void**)&v, g_v);
    cudaGetSymbolAddress((void**)&c, g_c);

    const int M1 = BB * NN;  // 16384

    // 1. a = S @ Win^T   (plain TF32: errors attenuated by /pairs and *0.3)
    tgemm<0, true, false><<<dim3(DD / 128, M1 / 128, 1), 256>>>(
        S, Win, u, M1, DD, DD, 0, 0, 0, nullptr, nullptr, 0.0f);

    // 2. normalize pairs in place (u becomes cos/sin interleaved)
    long long np = (long long)BB * NN * (DD / 2);
    pairnorm_kernel<<<(int)((np + 255) / 256), 256>>>(u, np);

    // 3. racc_new = clip(0.7*racc + (0.3/pairs) * U U^T, -2, 2)  (plain TF32, batched NT)
    tgemm<2, true, false><<<dim3(NN / 128, NN / 128, BB), 256>>>(
        u, u, raccO, NN, NN, DD,
        (long long)NN * DD, (long long)NN * DD, (long long)NN * NN,
        nullptr, Racc, 0.3f / (float)(DD / 2));

    // 4. coupling rows (sigmoid, gates, zero-diag, normalize)
    coupling_kernel<<<dim3(NN, BB), 256>>>(raccO, G, cond, c);

    // 5. values = (S * g) @ Wout^T  (TF32x3 corrected — feeds output directly)
    tgemm<1, true, true><<<dim3(DD / 128, M1 / 128, 1), 256>>>(
        S, Wout, v, M1, DD, DD, 0, 0, 0, G, nullptr, 0.0f);

    // 6. field = coupling @ values  (TF32x3 corrected, batched NN)
    tgemm<0, false, true><<<dim3(DD / 128, NN / 128, BB), 256>>>(
        c, v, field, NN, DD, NN,
        (long long)NN * NN, (long long)NN * DD, (long long)NN * DD,
        nullptr, nullptr, 0.0f);
}

// round 4
// speedup vs baseline: 3.2695x; 2.6229x over previous
#include <cuda_runtime.h>
#include <cuda_bf16.h>
#include <math.h>
#include <stdint.h>

#define BB 8
#define NN 2048
#define DD 1024
typedef long long ll;
typedef __nv_bfloat16 bf16;

// ---------------- scratch (allocation-free rule: __device__ globals) ----------
__device__ float g_u[BB * NN * DD];        // GEMM1 out (field_in), f32
__device__ float g_v[BB * NN * DD];        // GEMM5 out (values), f32
__device__ bf16  g_uh[BB * NN * DD];       // normalized pairs, bf16
__device__ bf16  g_vth[BB * DD * NN];      // values^T hi
__device__ bf16  g_vtl[BB * DD * NN];      // values^T lo
__device__ bf16  g_ch[(ll)BB * NN * NN];   // coupling hi
__device__ bf16  g_cl[(ll)BB * NN * NN];   // coupling lo
__device__ bf16  g_sh[BB * NN * DD];       // S hi (ungated)
__device__ bf16  g_sgh[BB * NN * DD];      // S*g hi
__device__ bf16  g_sgl[BB * NN * DD];      // S*g lo
__device__ bf16  g_wh[DD * DD];            // W_in hi
__device__ bf16  g_woh[DD * DD];           // W_out hi
__device__ bf16  g_wol[DD * DD];           // W_out lo

// ---------------- PTX helpers ------------------------------------------------
__device__ __forceinline__ uint32_t smem_u32(const void* p) {
    uint32_t a;
    asm("{ .reg .u64 t; cvta.to.shared.u64 t, %1; cvt.u32.u64 %0, t; }" : "=r"(a) : "l"(p));
    return a;
}
__device__ __forceinline__ void cpa16(uint32_t d, const void* s) {
    asm volatile("cp.async.cg.shared.global [%0], [%1], 16;" :: "r"(d), "l"(s));
}
__device__ __forceinline__ void cp_commit() { asm volatile("cp.async.commit_group;"); }
template <int N> __device__ __forceinline__ void cp_wait() {
    asm volatile("cp.async.wait_group %0;" :: "n"(N));
}
__device__ __forceinline__ void mma16(float* c, const uint32_t* a, const uint32_t* b) {
    asm volatile(
        "mma.sync.aligned.m16n8k16.row.col.f32.bf16.bf16.f32 "
        "{%0,%1,%2,%3}, {%4,%5,%6,%7}, {%8,%9}, {%0,%1,%2,%3};"
        : "+f"(c[0]), "+f"(c[1]), "+f"(c[2]), "+f"(c[3])
        : "r"(a[0]), "r"(a[1]), "r"(a[2]), "r"(a[3]), "r"(b[0]), "r"(b[1]));
}

// Tile geometry: 128x128 block, BK=32, 8 warps (2x4), warp tile 64x32.
// Smem K-major rows padded: 32 data + 8 pad bf16 = 80B stride (conflict-free).
#define PADW 40                      // bf16 per smem row
#define TILE_B (128 * PADW * 2)      // 10240 bytes per 128x32 tile

// EPI: 0 = plain f32 store; 2 = resonance clip-lerp epilogue.
// CORR: bf16 split, D += Ah*Bh + Ah*Bl + Al*Bh.
template <int EPI, bool CORR>
__global__ __launch_bounds__(256) void hgemm(
    const bf16* __restrict__ Ahg, const bf16* __restrict__ Alg,
    const bf16* __restrict__ Bhg, const bf16* __restrict__ Blg,
    float* __restrict__ Cg, int K, int ldC,
    ll sA, ll sB, ll sC,
    const float* __restrict__ raccIn, float resScale)
{
    extern __shared__ char dsm[];
    const int tid = threadIdx.x, lane = tid & 31, warp = tid >> 5;
    const int mq = lane >> 2, kq = lane & 3;
    const int wm = (warp >> 2) * 64, wn = (warp & 3) * 32;
    const int b = blockIdx.z;
    const int rowBlock = blockIdx.y * 128, colBlock = blockIdx.x * 128;

    const bf16* Ahp = Ahg + (ll)b * sA + (ll)rowBlock * K;
    const bf16* Bhp = Bhg + (ll)b * sB + (ll)colBlock * K;
    const bf16* Alp = CORR ? (Alg + (ll)b * sA + (ll)rowBlock * K) : nullptr;
    const bf16* Blp = CORR ? (Blg + (ll)b * sB + (ll)colBlock * K) : nullptr;
    float* C = Cg + (ll)b * sC;

    const int NT = CORR ? 4 : 2;             // tiles per buffer
    const uint32_t BUFB = (uint32_t)NT * TILE_B;
    uint32_t smem = smem_u32(dsm);

    float acc[4][4][4];
#pragma unroll
    for (int i = 0; i < 4; i++)
#pragma unroll
        for (int j = 0; j < 4; j++)
#pragma unroll
            for (int r = 0; r < 4; r++) acc[i][j][r] = 0.0f;

    // One 128x32 tile = 512 16B chunks; 256 threads x 2.
    auto load_tile = [&](uint32_t ts, const bf16* g, int k0) {
#pragma unroll
        for (int h = 0; h < 2; h++) {
            int f = tid + h * 256;
            int r = f >> 2, c = f & 3;
            cpa16(ts + r * (PADW * 2) + c * 16, g + (ll)r * K + k0 + c * 8);
        }
    };
    auto prefetch = [&](int ch) {
        uint32_t bo = smem + (uint32_t)(ch & 1) * BUFB;
        int k0 = ch * 32;
        load_tile(bo, Ahp, k0);
        load_tile(bo + TILE_B, Bhp, k0);
        if (CORR) {
            load_tile(bo + 2 * TILE_B, Alp, k0);
            load_tile(bo + 3 * TILE_B, Blp, k0);
        }
        cp_commit();
    };

    const int CH = K >> 5;
    prefetch(0);

    for (int ch = 0; ch < CH; ++ch) {
        if (ch + 1 < CH) { prefetch(ch + 1); cp_wait<1>(); }
        else             { cp_wait<0>(); }
        __syncthreads();

        uint32_t bo = smem + (uint32_t)(ch & 1) * BUFB;
        const uint32_t* Ah32 = (const uint32_t*)(uintptr_t)0;  // placate compiler
        (void)Ah32;
        const uint32_t* AsH = (const uint32_t*)(dsm + (bo - smem));
        const uint32_t* BsH = (const uint32_t*)(dsm + (bo - smem) + TILE_B);
        const uint32_t* AsL = CORR ? (const uint32_t*)(dsm + (bo - smem) + 2 * TILE_B) : nullptr;
        const uint32_t* BsL = CORR ? (const uint32_t*)(dsm + (bo - smem) + 3 * TILE_B) : nullptr;

#pragma unroll
        for (int ks = 0; ks < 2; ks++) {
            const int kp = ks * 16 + 2 * kq;        // bf16 index of k-pair
            const int ku = kp >> 1;                 // u32 index
            uint32_t ah[4][4], bh[4][2];
            uint32_t al[4][4], bl[4][2];
#pragma unroll
            for (int i = 0; i < 4; i++) {
                int m = wm + i * 16 + mq;
                ah[i][0] = AsH[m * (PADW / 2) + ku];
                ah[i][1] = AsH[(m + 8) * (PADW / 2) + ku];
                ah[i][2] = AsH[m * (PADW / 2) + ku + 4];
                ah[i][3] = AsH[(m + 8) * (PADW / 2) + ku + 4];
                if (CORR) {
                    al[i][0] = AsL[m * (PADW / 2) + ku];
                    al[i][1] = AsL[(m + 8) * (PADW / 2) + ku];
                    al[i][2] = AsL[m * (PADW / 2) + ku + 4];
                    al[i][3] = AsL[(m + 8) * (PADW / 2) + ku + 4];
                }
            }
#pragma unroll
            for (int j = 0; j < 4; j++) {
                int n = wn + j * 8 + mq;
                bh[j][0] = BsH[n * (PADW / 2) + ku];
                bh[j][1] = BsH[n * (PADW / 2) + ku + 4];
                if (CORR) {
                    bl[j][0] = BsL[n * (PADW / 2) + ku];
                    bl[j][1] = BsL[n * (PADW / 2) + ku + 4];
                }
            }
#pragma unroll
            for (int i = 0; i < 4; i++)
#pragma unroll
                for (int j = 0; j < 4; j++) {
                    mma16(acc[i][j], ah[i], bh[j]);
                    if (CORR) {
                        mma16(acc[i][j], ah[i], bl[j]);
                        mma16(acc[i][j], al[i], bh[j]);
                    }
                }
        }
        __syncthreads();
    }

    // ---- epilogue: float2 stores ----
#pragma unroll
    for (int i = 0; i < 4; i++) {
        int r0 = rowBlock + wm + i * 16 + mq;
#pragma unroll
        for (int j = 0; j < 4; j++) {
            int c0 = colBlock + wn + j * 8 + 2 * kq;
#pragma unroll
            for (int h = 0; h < 2; h++) {
                int rr = r0 + h * 8;
                float x = acc[i][j][h * 2 + 0];
                float y = acc[i][j][h * 2 + 1];
                ll off = (ll)rr * ldC + c0;
                if (EPI == 2) {
                    float2 rv = *(const float2*)(raccIn + (ll)b * sC + off);
                    x = fminf(fmaxf(0.7f * rv.x + resScale * x, -2.0f), 2.0f);
                    y = fminf(fmaxf(0.7f * rv.y + resScale * y, -2.0f), 2.0f);
                }
                *(float2*)(C + off) = make_float2(x, y);
            }
        }
    }
}

// ---------------- elementwise kernels ----------------------------------------
__device__ __forceinline__ void split_bf16(float x, bf16& h, bf16& l) {
    h = __float2bfloat16(x);
    l = __float2bfloat16(x - __bfloat162float(h));
}

__global__ void conv_s_kernel(const float* __restrict__ S, const float* __restrict__ G,
                              bf16* __restrict__ Sh, bf16* __restrict__ SGh,
                              bf16* __restrict__ SGl) {
    ll i = (ll)blockIdx.x * blockDim.x + threadIdx.x;
    if (i >= (ll)BB * NN * DD) return;
    float s = S[i];
    Sh[i] = __float2bfloat16(s);
    float t = s * G[i >> 10];
    bf16 h, l; split_bf16(t, h, l);
    SGh[i] = h; SGl[i] = l;
}

__global__ void conv_w_kernel(const float* __restrict__ Win, const float* __restrict__ Wout,
                              bf16* __restrict__ Wh, bf16* __restrict__ Woh,
                              bf16* __restrict__ Wol) {
    int i = blockIdx.x * blockDim.x + threadIdx.x;
    if (i >= DD * DD) return;
    Wh[i] = __float2bfloat16(Win[i]);
    bf16 h, l; split_bf16(Wout[i], h, l);
    Woh[i] = h; Wol[i] = l;
}

// cos(atan2(y+e,x+e)) = (x+e)/r, sin = (y+e)/r -> normalized bf16 pairs
__global__ void pairnorm_kernel(const float* __restrict__ a, bf16* __restrict__ uh,
                                ll nPairs) {
    ll i = (ll)blockIdx.x * blockDim.x + threadIdx.x;
    if (i >= nPairs) return;
    float2 v = ((const float2*)a)[i];
    float x = v.x + 1e-8f;
    float y = v.y + 1e-8f;
    float inv = rsqrtf(x * x + y * y);
    uh[2 * i]     = __float2bfloat16(x * inv);
    uh[2 * i + 1] = __float2bfloat16(y * inv);
}

// per (b,n) row: sigmoid, gates, zero diag, row-normalize -> bf16 hi/lo
__global__ __launch_bounds__(256) void coupling_kernel(
    const float* __restrict__ raccNew, const float* __restrict__ gates,
    const float* __restrict__ condPtr, bf16* __restrict__ ch, bf16* __restrict__ cl)
{
    int n = blockIdx.x, b = blockIdx.y;
    const float* row = raccNew + ((ll)b * NN + n) * NN;
    ll obase = ((ll)b * NN + n) * NN;
    float cond = fminf(fmaxf(condPtr[0], -5.0f), 5.0f);
    float gn = gates[b * NN + n];
    int t = threadIdx.x;
    float local[NN / 256];
    float sum = 0.0f;
#pragma unroll
    for (int it = 0; it < NN / 256; it++) {
        int m = t + it * 256;
        float s = 1.0f / (1.0f + expf(-cond * row[m]));
        float c = s * gates[b * NN + m] * gn;
        if (m == n) c = 0.0f;
        local[it] = c;
        sum += c;
    }
    __shared__ float red[256];
    red[t] = sum;
    __syncthreads();
    for (int s = 128; s > 0; s >>= 1) {
        if (t < s) red[t] += red[t + s];
        __syncthreads();
    }
    float inv = 1.0f / (red[0] + 1e-8f);
#pragma unroll
    for (int it = 0; it < NN / 256; it++) {
        float c = local[it] * inv;
        bf16 h, l; split_bf16(c, h, l);
        ch[obase + t + it * 256] = h;
        cl[obase + t + it * 256] = l;
    }
}

// v (b,n,d) f32 -> vT (b,d,n) bf16 hi/lo, 32x32 smem tiles
__global__ void vtrans_kernel(const float* __restrict__ v,
                              bf16* __restrict__ th, bf16* __restrict__ tl) {
    __shared__ float t[32][33];
    int b = blockIdx.z;
    int n0 = blockIdx.x * 32, d0 = blockIdx.y * 32;
    const float* vb = v + (ll)b * NN * DD;
#pragma unroll
    for (int i = 0; i < 32; i += 8)
        t[threadIdx.y + i][threadIdx.x] =
            vb[(ll)(n0 + threadIdx.y + i) * DD + d0 + threadIdx.x];
    __syncthreads();
    ll ob = (ll)b * DD * NN;
#pragma unroll
    for (int i = 0; i < 32; i += 8) {
        float val = t[threadIdx.x][threadIdx.y + i];
        ll idx = ob + (ll)(d0 + threadIdx.y + i) * NN + n0 + threadIdx.x;
        bf16 h, l; split_bf16(val, h, l);
        th[idx] = h; tl[idx] = l;
    }
}

// ---------------- launch -----------------------------------------------------
extern "C" void kernel_launch(void* const* d_in, const int* in_sizes, int n_in,
                              void* d_out, int out_size) {
    const float* S    = (const float*)d_in[0];
    const float* G    = (const float*)d_in[1];
    const float* Racc = (const float*)d_in[2];
    const float* Win  = (const float*)d_in[3];
    const float* Wout = (const float*)d_in[4];
    const float* cond = (const float*)d_in[5];

    float* field = (float*)d_out;                 // (B,N,D)
    float* raccO = field + (size_t)BB * NN * DD;  // (B,N,N)

    float *u, *v;
    bf16 *uh, *vth, *vtl, *ch, *cl, *sh, *sgh, *sgl, *wh, *woh, *wol;
    cudaGetSymbolAddress((void**)&u, g_u);
    cudaGetSymbolAddress((void**)&v, g_v);
    cudaGetSymbolAddress((void**)&uh, g_uh);
    cudaGetSymbolAddress((void**)&vth, g_vth);
    cudaGetSymbolAddress((void**)&vtl, g_vtl);
    cudaGetSymbolAddress((void**)&ch, g_ch);
    cudaGetSymbolAddress((void**)&cl, g_cl);
    cudaGetSymbolAddress((void**)&sh, g_sh);
    cudaGetSymbolAddress((void**)&sgh, g_sgh);
    cudaGetSymbolAddress((void**)&sgl, g_sgl);
    cudaGetSymbolAddress((void**)&wh, g_wh);
    cudaGetSymbolAddress((void**)&woh, g_woh);
    cudaGetSymbolAddress((void**)&wol, g_wol);

    const int SM_PLAIN = 2 * 2 * TILE_B;  // 40960 (fits default 48K)
    const int SM_CORR  = 2 * 4 * TILE_B;  // 81920 (needs opt-in)
    cudaFuncSetAttribute(hgemm<0, true>, cudaFuncAttributeMaxDynamicSharedMemorySize, SM_CORR);

    const ll M1 = (ll)BB * NN;  // 16384

    // 0. conversions
    conv_s_kernel<<<(int)((M1 * DD + 255) / 256), 256>>>(S, G, sh, sgh, sgl);
    conv_w_kernel<<<(DD * DD + 255) / 256, 256>>>(Win, Wout, wh, woh, wol);

    // 1. u = S @ Win^T   (plain bf16: errors attenuated downstream)
    hgemm<0, false><<<dim3(DD / 128, (int)(M1 / 128), 1), 256, SM_PLAIN>>>(
        sh, nullptr, wh, nullptr, u, DD, DD, 0, 0, 0, nullptr, 0.0f);

    // 2. normalize pairs -> uh (bf16)
    ll np = (ll)BB * NN * (DD / 2);
    pairnorm_kernel<<<(int)((np + 255) / 256), 256>>>(u, uh, np);

    // 3. raccO = clip(0.7*racc + (0.3/pairs) * U U^T, -2, 2)   (batched NT, plain)
    hgemm<2, false><<<dim3(NN / 128, NN / 128, BB), 256, SM_PLAIN>>>(
        uh, nullptr, uh, nullptr, raccO, DD, NN,
        (ll)NN * DD, (ll)NN * DD, (ll)NN * NN, Racc, 0.3f / (float)(DD / 2));

    // 4. coupling rows -> bf16 hi/lo
    coupling_kernel<<<dim3(NN, BB), 256>>>(raccO, G, cond, ch, cl);

    // 5. v = (S*g) @ Wout^T   (bf16 split corrected)
    hgemm<0, true><<<dim3(DD / 128, (int)(M1 / 128), 1), 256, SM_CORR>>>(
        sgh, sgl, woh, wol, v, DD, DD, 0, 0, 0, nullptr, 0.0f);

    // 5b. transpose v -> vT bf16 hi/lo
    vtrans_kernel<<<dim3(NN / 32, DD / 32, BB), dim3(32, 8)>>>(v, vth, vtl);

    // 6. field = coupling @ values   (batched, bf16 split corrected)
    hgemm<0, true><<<dim3(DD / 128, NN / 128, BB), 256, SM_CORR>>>(
        ch, cl, vth, vtl, field, NN, DD,
        (ll)NN * NN, (ll)DD * NN, (ll)NN * DD, nullptr, 0.0f);
}

// round 5
// speedup vs baseline: 3.4339x; 1.0503x over previous
#include <cuda_runtime.h>
#include <cuda_bf16.h>
#include <math.h>
#include <stdint.h>

#define BB 8
#define NN 2048
#define DD 1024
typedef long long ll;
typedef __nv_bfloat16 bf16;

// ---------------- scratch (allocation-free rule: __device__ globals) ----------
__device__ float g_v[BB * NN * DD];        // GEMM5 out (values), f32
__device__ bf16  g_uh[BB * NN * DD];       // normalized pairs, bf16 (GEMM1 fused out)
__device__ bf16  g_vth[BB * DD * NN];      // values^T hi
__device__ bf16  g_vtl[BB * DD * NN];      // values^T lo
__device__ bf16  g_ch[(ll)BB * NN * NN];   // coupling hi
__device__ bf16  g_cl[(ll)BB * NN * NN];   // coupling lo
__device__ bf16  g_sh[BB * NN * DD];       // S hi (ungated)
__device__ bf16  g_sgh[BB * NN * DD];      // S*g hi
__device__ bf16  g_sgl[BB * NN * DD];      // S*g lo
__device__ bf16  g_wh[DD * DD];            // W_in hi
__device__ bf16  g_woh[DD * DD];           // W_out hi
__device__ bf16  g_wol[DD * DD];           // W_out lo

// ---------------- PTX helpers ------------------------------------------------
__device__ __forceinline__ uint32_t smem_u32(const void* p) {
    uint32_t a;
    asm("{ .reg .u64 t; cvta.to.shared.u64 t, %1; cvt.u32.u64 %0, t; }" : "=r"(a) : "l"(p));
    return a;
}
__device__ __forceinline__ void cpa16(uint32_t d, const void* s) {
    asm volatile("cp.async.cg.shared.global [%0], [%1], 16;" :: "r"(d), "l"(s));
}
__device__ __forceinline__ void cp_commit() { asm volatile("cp.async.commit_group;"); }
template <int N> __device__ __forceinline__ void cp_wait() {
    asm volatile("cp.async.wait_group %0;" :: "n"(N));
}
__device__ __forceinline__ void mma16(float* c, const uint32_t* a, const uint32_t* b) {
    asm volatile(
        "mma.sync.aligned.m16n8k16.row.col.f32.bf16.bf16.f32 "
        "{%0,%1,%2,%3}, {%4,%5,%6,%7}, {%8,%9}, {%0,%1,%2,%3};"
        : "+f"(c[0]), "+f"(c[1]), "+f"(c[2]), "+f"(c[3])
        : "r"(a[0]), "r"(a[1]), "r"(a[2]), "r"(a[3]), "r"(b[0]), "r"(b[1]));
}
__device__ __forceinline__ void ldsm4(uint32_t* r, uint32_t addr) {
    asm volatile("ldmatrix.sync.aligned.m8n8.x4.shared.b16 {%0,%1,%2,%3}, [%4];"
        : "=r"(r[0]), "=r"(r[1]), "=r"(r[2]), "=r"(r[3]) : "r"(addr));
}

// Tile geometry: 128x128 block, BK=64, 8 warps (2x4), warp tile 64x32.
// Smem K-major rows: 64 data + 8 pad bf16 = 144B stride (16 mod 128 -> ldmatrix
// rows hit 8 distinct 16B banks; conflict-free).
#define ROWB 144
#define TILE_B (128 * ROWB)          // 18432 bytes per 128x64 tile

// EPI: 0 = plain f32 store; 2 = resonance clip-lerp; 3 = fused pairnorm -> bf16
// CORR: bf16 split, D += Ah*Bh + Ah*Bl + Al*Bh.
template <int EPI, bool CORR>
__global__ __launch_bounds__(256) void hgemm(
    const bf16* __restrict__ Ahg, const bf16* __restrict__ Alg,
    const bf16* __restrict__ Bhg, const bf16* __restrict__ Blg,
    float* __restrict__ Cg, int K, int ldC,
    ll sA, ll sB, ll sC,
    const float* __restrict__ raccIn, float resScale)
{
    extern __shared__ char dsm[];
    const int tid = threadIdx.x, lane = tid & 31, warp = tid >> 5;
    const int mq = lane >> 2, kq = lane & 3;
    const int wm = (warp >> 2) * 64, wn = (warp & 3) * 32;
    const int b = blockIdx.z;
    const int rowBlock = blockIdx.y * 128, colBlock = blockIdx.x * 128;

    const bf16* Ahp = Ahg + (ll)b * sA + (ll)rowBlock * K;
    const bf16* Bhp = Bhg + (ll)b * sB + (ll)colBlock * K;
    const bf16* Alp = CORR ? (Alg + (ll)b * sA + (ll)rowBlock * K) : nullptr;
    const bf16* Blp = CORR ? (Blg + (ll)b * sB + (ll)colBlock * K) : nullptr;
    float* C = Cg + (ll)b * sC;

    const uint32_t BUFB = (CORR ? 4u : 2u) * TILE_B;
    uint32_t smem = smem_u32(dsm);

    // ldmatrix per-lane addressing within a 16x16 b16 tile quartet
    const int sub = lane >> 3, l7 = lane & 7;
    const uint32_t lmoff = (uint32_t)(((sub & 1) * 8 + l7) * ROWB + (sub >> 1) * 16);

    float acc[4][4][4];
#pragma unroll
    for (int i = 0; i < 4; i++)
#pragma unroll
        for (int j = 0; j < 4; j++)
#pragma unroll
            for (int r = 0; r < 4; r++) acc[i][j][r] = 0.0f;

    // One 128x64 tile = 1024 x 16B transfers; 256 threads x 4.
    auto load_tile = [&](uint32_t ts, const bf16* g, int k0) {
#pragma unroll
        for (int h = 0; h < 4; h++) {
            int f = tid + h * 256;
            int r = f >> 3, c = f & 7;
            cpa16(ts + r * ROWB + c * 16, g + (ll)r * K + k0 + c * 8);
        }
    };
    auto prefetch = [&](int ch) {
        uint32_t bo = smem + (uint32_t)(ch & 1) * BUFB;
        int k0 = ch * 64;
        load_tile(bo, Ahp, k0);
        load_tile(bo + TILE_B, Bhp, k0);
        if (CORR) {
            load_tile(bo + 2 * TILE_B, Alp, k0);
            load_tile(bo + 3 * TILE_B, Blp, k0);
        }
        cp_commit();
    };

    const int CH = K >> 6;
    prefetch(0);

    for (int ch = 0; ch < CH; ++ch) {
        if (ch + 1 < CH) { prefetch(ch + 1); cp_wait<1>(); }
        else             { cp_wait<0>(); }
        __syncthreads();

        uint32_t bo = smem + (uint32_t)(ch & 1) * BUFB;
        uint32_t AsH = bo, BsH = bo + TILE_B;
        uint32_t AsL = bo + 2 * TILE_B, BsL = bo + 3 * TILE_B;

#pragma unroll
        for (int ks = 0; ks < 4; ks++) {
            const uint32_t ko = (uint32_t)ks * 32;  // 16 bf16 = 32B per k-step
            uint32_t af[4][4], bfr[4][2];
            uint32_t alf[4][4], blf[4][2];
#pragma unroll
            for (int i = 0; i < 4; i++)
                ldsm4(af[i], AsH + (uint32_t)(wm + i * 16) * ROWB + lmoff + ko);
#pragma unroll
            for (int jj = 0; jj < 2; jj++) {
                uint32_t t[4];
                ldsm4(t, BsH + (uint32_t)(wn + jj * 16) * ROWB + lmoff + ko);
                bfr[2 * jj][0] = t[0]; bfr[2 * jj + 1][0] = t[1];
                bfr[2 * jj][1] = t[2]; bfr[2 * jj + 1][1] = t[3];
            }
            if (CORR) {
#pragma unroll
                for (int i = 0; i < 4; i++)
                    ldsm4(alf[i], AsL + (uint32_t)(wm + i * 16) * ROWB + lmoff + ko);
#pragma unroll
                for (int jj = 0; jj < 2; jj++) {
                    uint32_t t[4];
                    ldsm4(t, BsL + (uint32_t)(wn + jj * 16) * ROWB + lmoff + ko);
                    blf[2 * jj][0] = t[0]; blf[2 * jj + 1][0] = t[1];
                    blf[2 * jj][1] = t[2]; blf[2 * jj + 1][1] = t[3];
                }
            }
#pragma unroll
            for (int i = 0; i < 4; i++)
#pragma unroll
                for (int j = 0; j < 4; j++) {
                    mma16(acc[i][j], af[i], bfr[j]);
                    if (CORR) {
                        mma16(acc[i][j], af[i], blf[j]);
                        mma16(acc[i][j], alf[i], bfr[j]);
                    }
                }
        }
        __syncthreads();
    }

    // ---- epilogue ----
#pragma unroll
    for (int i = 0; i < 4; i++) {
        int r0 = rowBlock + wm + i * 16 + mq;
#pragma unroll
        for (int j = 0; j < 4; j++) {
            int c0 = colBlock + wn + j * 8 + 2 * kq;
#pragma unroll
            for (int h = 0; h < 2; h++) {
                int rr = r0 + h * 8;
                float x = acc[i][j][h * 2 + 0];
                float y = acc[i][j][h * 2 + 1];
                ll off = (ll)rr * ldC + c0;
                if (EPI == 3) {
                    // fused pairnorm: (x,y) is an even-aligned (cos,sin) pre-pair
                    float xn = x + 1e-8f, yn = y + 1e-8f;
                    float inv = rsqrtf(xn * xn + yn * yn);
                    __nv_bfloat162 h2 = __floats2bfloat162_rn(xn * inv, yn * inv);
                    *(uint32_t*)((bf16*)Cg + (ll)b * sC + off) =
                        *(uint32_t*)&h2;
                } else {
                    if (EPI == 2) {
                        float2 rv = *(const float2*)(raccIn + (ll)b * sC + off);
                        x = fminf(fmaxf(0.7f * rv.x + resScale * x, -2.0f), 2.0f);
                        y = fminf(fmaxf(0.7f * rv.y + resScale * y, -2.0f), 2.0f);
                    }
                    *(float2*)(C + off) = make_float2(x, y);
                }
            }
        }
    }
}

// ---------------- elementwise kernels ----------------------------------------
__device__ __forceinline__ void split_bf16(float x, bf16& h, bf16& l) {
    h = __float2bfloat16(x);
    l = __float2bfloat16(x - __bfloat162float(h));
}

__global__ void conv_s_kernel(const float* __restrict__ S, const float* __restrict__ G,
                              bf16* __restrict__ Sh, bf16* __restrict__ SGh,
                              bf16* __restrict__ SGl) {
    ll i = (ll)blockIdx.x * blockDim.x + threadIdx.x;
    if (i >= (ll)BB * NN * DD) return;
    float s = S[i];
    Sh[i] = __float2bfloat16(s);
    float t = s * G[i >> 10];
    bf16 h, l; split_bf16(t, h, l);
    SGh[i] = h; SGl[i] = l;
}

__global__ void conv_w_kernel(const float* __restrict__ Win, const float* __restrict__ Wout,
                              bf16* __restrict__ Wh, bf16* __restrict__ Woh,
                              bf16* __restrict__ Wol) {
    int i = blockIdx.x * blockDim.x + threadIdx.x;
    if (i >= DD * DD) return;
    Wh[i] = __float2bfloat16(Win[i]);
    bf16 h, l; split_bf16(Wout[i], h, l);
    Woh[i] = h; Wol[i] = l;
}

// per (b,n) row: sigmoid, gates, zero diag, row-normalize -> bf16 hi/lo
__global__ __launch_bounds__(256) void coupling_kernel(
    const float* __restrict__ raccNew, const float* __restrict__ gates,
    const float* __restrict__ condPtr, bf16* __restrict__ ch, bf16* __restrict__ cl)
{
    int n = blockIdx.x, b = blockIdx.y;
    const float* row = raccNew + ((ll)b * NN + n) * NN;
    ll obase = ((ll)b * NN + n) * NN;
    float cond = fminf(fmaxf(condPtr[0], -5.0f), 5.0f);
    float gn = gates[b * NN + n];
    int t = threadIdx.x;
    float local[NN / 256];
    float sum = 0.0f;
#pragma unroll
    for (int it = 0; it < NN / 256; it++) {
        int m = t + it * 256;
        float s = 1.0f / (1.0f + expf(-cond * row[m]));
        float c = s * gates[b * NN + m] * gn;
        if (m == n) c = 0.0f;
        local[it] = c;
        sum += c;
    }
    __shared__ float red[256];
    red[t] = sum;
    __syncthreads();
    for (int s = 128; s > 0; s >>= 1) {
        if (t < s) red[t] += red[t + s];
        __syncthreads();
    }
    float inv = 1.0f / (red[0] + 1e-8f);
#pragma unroll
    for (int it = 0; it < NN / 256; it++) {
        float c = local[it] * inv;
        bf16 h, l; split_bf16(c, h, l);
        ch[obase + t + it * 256] = h;
        cl[obase + t + it * 256] = l;
    }
}

// v (b,n,d) f32 -> vT (b,d,n) bf16 hi/lo, 32x32 smem tiles
__global__ void vtrans_kernel(const float* __restrict__ v,
                              bf16* __restrict__ th, bf16* __restrict__ tl) {
    __shared__ float t[32][33];
    int b = blockIdx.z;
    int n0 = blockIdx.x * 32, d0 = blockIdx.y * 32;
    const float* vb = v + (ll)b * NN * DD;
#pragma unroll
    for (int i = 0; i < 32; i += 8)
        t[threadIdx.y + i][threadIdx.x] =
            vb[(ll)(n0 + threadIdx.y + i) * DD + d0 + threadIdx.x];
    __syncthreads();
    ll ob = (ll)b * DD * NN;
#pragma unroll
    for (int i = 0; i < 32; i += 8) {
        float val = t[threadIdx.x][threadIdx.y + i];
        ll idx = ob + (ll)(d0 + threadIdx.y + i) * NN + n0 + threadIdx.x;
        bf16 h, l; split_bf16(val, h, l);
        th[idx] = h; tl[idx] = l;
    }
}

// ---------------- launch -----------------------------------------------------
extern "C" void kernel_launch(void* const* d_in, const int* in_sizes, int n_in,
                              void* d_out, int out_size) {
    const float* S    = (const float*)d_in[0];
    const float* G    = (const float*)d_in[1];
    const float* Racc = (const float*)d_in[2];
    const float* Win  = (const float*)d_in[3];
    const float* Wout = (const float*)d_in[4];
    const float* cond = (const float*)d_in[5];

    float* field = (float*)d_out;                 // (B,N,D)
    float* raccO = field + (size_t)BB * NN * DD;  // (B,N,N)

    float *v;
    bf16 *uh, *vth, *vtl, *ch, *cl, *sh, *sgh, *sgl, *wh, *woh, *wol;
    cudaGetSymbolAddress((void**)&v, g_v);
    cudaGetSymbolAddress((void**)&uh, g_uh);
    cudaGetSymbolAddress((void**)&vth, g_vth);
    cudaGetSymbolAddress((void**)&vtl, g_vtl);
    cudaGetSymbolAddress((void**)&ch, g_ch);
    cudaGetSymbolAddress((void**)&cl, g_cl);
    cudaGetSymbolAddress((void**)&sh, g_sh);
    cudaGetSymbolAddress((void**)&sgh, g_sgh);
    cudaGetSymbolAddress((void**)&sgl, g_sgl);
    cudaGetSymbolAddress((void**)&wh, g_wh);
    cudaGetSymbolAddress((void**)&woh, g_woh);
    cudaGetSymbolAddress((void**)&wol, g_wol);

    const int SM_PLAIN = 2 * 2 * TILE_B;  // 73728
    const int SM_CORR  = 2 * 4 * TILE_B;  // 147456
    cudaFuncSetAttribute(hgemm<3, false>, cudaFuncAttributeMaxDynamicSharedMemorySize, SM_PLAIN);
    cudaFuncSetAttribute(hgemm<2, false>, cudaFuncAttributeMaxDynamicSharedMemorySize, SM_PLAIN);
    cudaFuncSetAttribute(hgemm<0, true>,  cudaFuncAttributeMaxDynamicSharedMemorySize, SM_CORR);

    const ll M1 = (ll)BB * NN;  // 16384

    // 0. conversions
    conv_s_kernel<<<(int)((M1 * DD + 255) / 256), 256>>>(S, G, sh, sgh, sgl);
    conv_w_kernel<<<(DD * DD + 255) / 256, 256>>>(Win, Wout, wh, woh, wol);

    // 1+2. uh = pairnorm(S @ Win^T) fused   (plain bf16, bf16 pair output)
    hgemm<3, false><<<dim3(DD / 128, (int)(M1 / 128), 1), 256, SM_PLAIN>>>(
        sh, nullptr, wh, nullptr, (float*)uh, DD, DD, 0, 0, 0, nullptr, 0.0f);

    // 3. raccO = clip(0.7*racc + (0.3/pairs) * U U^T, -2, 2)   (batched NT, plain)
    hgemm<2, false><<<dim3(NN / 128, NN / 128, BB), 256, SM_PLAIN>>>(
        uh, nullptr, uh, nullptr, raccO, DD, NN,
        (ll)NN * DD, (ll)NN * DD, (ll)NN * NN, Racc, 0.3f / (float)(DD / 2));

    // 4. coupling rows -> bf16 hi/lo
    coupling_kernel<<<dim3(NN, BB), 256>>>(raccO, G, cond, ch, cl);

    // 5. v = (S*g) @ Wout^T   (bf16 split corrected)
    hgemm<0, true><<<dim3(DD / 128, (int)(M1 / 128), 1), 256, SM_CORR>>>(
        sgh, sgl, woh, wol, v, DD, DD, 0, 0, 0, nullptr, 0.0f);

    // 5b. transpose v -> vT bf16 hi/lo
    vtrans_kernel<<<dim3(NN / 32, DD / 32, BB), dim3(32, 8)>>>(v, vth, vtl);

    // 6. field = coupling @ values   (batched, bf16 split corrected)
    hgemm<0, true><<<dim3(DD / 128, NN / 128, BB), 256, SM_CORR>>>(
        ch, cl, vth, vtl, field, NN, DD,
        (ll)NN * NN, (ll)DD * NN, (ll)NN * DD, nullptr, 0.0f);
}

// round 6
// speedup vs baseline: 3.5145x; 1.0235x over previous
#include <cuda_runtime.h>
#include <cuda_bf16.h>
#include <math.h>
#include <stdint.h>

#define BB 8
#define NN 2048
#define DD 1024
typedef long long ll;
typedef __nv_bfloat16 bf16;

// ---------------- scratch (allocation-free rule: __device__ globals) ----------
__device__ float g_v[BB * NN * DD];        // GEMM5 out (values), f32
__device__ bf16  g_uh[BB * NN * DD];       // normalized pairs, bf16 (GEMM1 fused out)
__device__ bf16  g_vth[BB * DD * NN];      // values^T hi
__device__ bf16  g_vtl[BB * DD * NN];      // values^T lo
__device__ bf16  g_ch[(ll)BB * NN * NN];   // coupling hi
__device__ bf16  g_cl[(ll)BB * NN * NN];   // coupling lo
__device__ bf16  g_sh[BB * NN * DD];       // S hi (ungated)
__device__ bf16  g_sgh[BB * NN * DD];      // S*g hi
__device__ bf16  g_sgl[BB * NN * DD];      // S*g lo
__device__ bf16  g_wh[DD * DD];            // W_in hi
__device__ bf16  g_woh[DD * DD];           // W_out hi
__device__ bf16  g_wol[DD * DD];           // W_out lo

// ---------------- PTX helpers ------------------------------------------------
__device__ __forceinline__ uint32_t smem_u32(const void* p) {
    uint32_t a;
    asm("{ .reg .u64 t; cvta.to.shared.u64 t, %1; cvt.u32.u64 %0, t; }" : "=r"(a) : "l"(p));
    return a;
}
__device__ __forceinline__ void cpa16(uint32_t d, const void* s) {
    asm volatile("cp.async.cg.shared.global [%0], [%1], 16;" :: "r"(d), "l"(s));
}
__device__ __forceinline__ void cp_commit() { asm volatile("cp.async.commit_group;"); }
template <int N> __device__ __forceinline__ void cp_wait() {
    asm volatile("cp.async.wait_group %0;" :: "n"(N));
}
__device__ __forceinline__ void mma16(float* c, const uint32_t* a, const uint32_t* b) {
    asm volatile(
        "mma.sync.aligned.m16n8k16.row.col.f32.bf16.bf16.f32 "
        "{%0,%1,%2,%3}, {%4,%5,%6,%7}, {%8,%9}, {%0,%1,%2,%3};"
        : "+f"(c[0]), "+f"(c[1]), "+f"(c[2]), "+f"(c[3])
        : "r"(a[0]), "r"(a[1]), "r"(a[2]), "r"(a[3]), "r"(b[0]), "r"(b[1]));
}
__device__ __forceinline__ void ldsm4(uint32_t* r, uint32_t addr) {
    asm volatile("ldmatrix.sync.aligned.m8n8.x4.shared.b16 {%0,%1,%2,%3}, [%4];"
        : "=r"(r[0]), "=r"(r[1]), "=r"(r[2]), "=r"(r[3]) : "r"(addr));
}

// Tile geometry: 128x128 block, BK=32, 8 warps (2x4), warp tile 64x32.
// Smem K-major rows: 32 data + 8 pad bf16 = 80B stride (rows hit 8 distinct
// 16B banks mod 128 -> ldmatrix conflict-free). Small stages => 2 CTAs/SM.
#define ROWB 80
#define TILE_B (128 * ROWB)          // 10240 bytes per 128x32 tile

// EPI: 0 = plain f32 store; 2 = resonance clip-lerp; 3 = fused pairnorm -> bf16
// CORR: bf16 split, D += Ah*Bh + Ah*Bl + Al*Bh.
// SYM:  symmetric NT product; grid.x enumerates upper-tri tile pairs; epilogue
//       writes both (i,j) and (j,i) (EPI==2 only).
template <int EPI, bool CORR, bool SYM>
__global__ __launch_bounds__(256, 2) void hgemm(
    const bf16* __restrict__ Ahg, const bf16* __restrict__ Alg,
    const bf16* __restrict__ Bhg, const bf16* __restrict__ Blg,
    float* __restrict__ Cg, int K, int ldC,
    ll sA, ll sB, ll sC,
    const float* __restrict__ raccIn, float resScale)
{
    extern __shared__ char dsm[];
    const int tid = threadIdx.x, lane = tid & 31, warp = tid >> 5;
    const int mq = lane >> 2, kq = lane & 3;
    const int wm = (warp >> 2) * 64, wn = (warp & 3) * 32;
    const int b = blockIdx.z;

    int rowBlock, colBlock;
    if (SYM) {
        // decode upper-triangle pair (bi <= bj) from blockIdx.x
        int T = ldC >> 7;
        int t = blockIdx.x, bi = 0;
        while (t >= T - bi) { t -= T - bi; bi++; }
        rowBlock = bi * 128;
        colBlock = (bi + t) * 128;
    } else {
        rowBlock = blockIdx.y * 128;
        colBlock = blockIdx.x * 128;
    }

    const bf16* Ahp = Ahg + (ll)b * sA + (ll)rowBlock * K;
    const bf16* Bhp = Bhg + (ll)b * sB + (ll)colBlock * K;
    const bf16* Alp = CORR ? (Alg + (ll)b * sA + (ll)rowBlock * K) : nullptr;
    const bf16* Blp = CORR ? (Blg + (ll)b * sB + (ll)colBlock * K) : nullptr;
    float* C = Cg + (ll)b * sC;

    const uint32_t BUFB = (CORR ? 4u : 2u) * TILE_B;
    uint32_t smem = smem_u32(dsm);

    // ldmatrix per-lane addressing within a 16x16 b16 tile quartet
    const int sub = lane >> 3, l7 = lane & 7;
    const uint32_t lmoff = (uint32_t)(((sub & 1) * 8 + l7) * ROWB + (sub >> 1) * 16);

    float acc[4][4][4];
#pragma unroll
    for (int i = 0; i < 4; i++)
#pragma unroll
        for (int j = 0; j < 4; j++)
#pragma unroll
            for (int r = 0; r < 4; r++) acc[i][j][r] = 0.0f;

    // One 128x32 tile = 512 x 16B transfers; 256 threads x 2.
    auto load_tile = [&](uint32_t ts, const bf16* g, int k0) {
#pragma unroll
        for (int h = 0; h < 2; h++) {
            int f = tid + h * 256;
            int r = f >> 2, c = f & 3;
            cpa16(ts + r * ROWB + c * 16, g + (ll)r * K + k0 + c * 8);
        }
    };
    auto prefetch = [&](int ch) {
        uint32_t bo = smem + (uint32_t)(ch & 1) * BUFB;
        int k0 = ch * 32;
        load_tile(bo, Ahp, k0);
        load_tile(bo + TILE_B, Bhp, k0);
        if (CORR) {
            load_tile(bo + 2 * TILE_B, Alp, k0);
            load_tile(bo + 3 * TILE_B, Blp, k0);
        }
        cp_commit();
    };

    const int CH = K >> 5;
    prefetch(0);

    for (int ch = 0; ch < CH; ++ch) {
        if (ch + 1 < CH) { prefetch(ch + 1); cp_wait<1>(); }
        else             { cp_wait<0>(); }
        __syncthreads();

        uint32_t bo = smem + (uint32_t)(ch & 1) * BUFB;
        uint32_t AsH = bo, BsH = bo + TILE_B;
        uint32_t AsL = bo + 2 * TILE_B, BsL = bo + 3 * TILE_B;

#pragma unroll
        for (int ks = 0; ks < 2; ks++) {
            const uint32_t ko = (uint32_t)ks * 32;  // 16 bf16 = 32B per k-step
            uint32_t af[4][4], bfr[4][2];
            uint32_t alf[4][4], blf[4][2];
#pragma unroll
            for (int i = 0; i < 4; i++)
                ldsm4(af[i], AsH + (uint32_t)(wm + i * 16) * ROWB + lmoff + ko);
#pragma unroll
            for (int jj = 0; jj < 2; jj++) {
                uint32_t t[4];
                ldsm4(t, BsH + (uint32_t)(wn + jj * 16) * ROWB + lmoff + ko);
                bfr[2 * jj][0] = t[0]; bfr[2 * jj + 1][0] = t[1];
                bfr[2 * jj][1] = t[2]; bfr[2 * jj + 1][1] = t[3];
            }
            if (CORR) {
#pragma unroll
                for (int i = 0; i < 4; i++)
                    ldsm4(alf[i], AsL + (uint32_t)(wm + i * 16) * ROWB + lmoff + ko);
#pragma unroll
                for (int jj = 0; jj < 2; jj++) {
                    uint32_t t[4];
                    ldsm4(t, BsL + (uint32_t)(wn + jj * 16) * ROWB + lmoff + ko);
                    blf[2 * jj][0] = t[0]; blf[2 * jj + 1][0] = t[1];
                    blf[2 * jj][1] = t[2]; blf[2 * jj + 1][1] = t[3];
                }
            }
#pragma unroll
            for (int i = 0; i < 4; i++)
#pragma unroll
                for (int j = 0; j < 4; j++) {
                    mma16(acc[i][j], af[i], bfr[j]);
                    if (CORR) {
                        mma16(acc[i][j], af[i], blf[j]);
                        mma16(acc[i][j], alf[i], bfr[j]);
                    }
                }
        }
        __syncthreads();
    }

    // ---- epilogue ----
    const float* raccB = (EPI == 2) ? (raccIn + (ll)b * sC) : nullptr;
    const bool mirror = SYM && (rowBlock != colBlock);
#pragma unroll
    for (int i = 0; i < 4; i++) {
        int r0 = rowBlock + wm + i * 16 + mq;
#pragma unroll
        for (int j = 0; j < 4; j++) {
            int c0 = colBlock + wn + j * 8 + 2 * kq;
#pragma unroll
            for (int h = 0; h < 2; h++) {
                int rr = r0 + h * 8;
                float x = acc[i][j][h * 2 + 0];
                float y = acc[i][j][h * 2 + 1];
                ll off = (ll)rr * ldC + c0;
                if (EPI == 3) {
                    float xn = x + 1e-8f, yn = y + 1e-8f;
                    float inv = rsqrtf(xn * xn + yn * yn);
                    __nv_bfloat162 h2 = __floats2bfloat162_rn(xn * inv, yn * inv);
                    *(uint32_t*)((bf16*)Cg + (ll)b * sC + off) = *(uint32_t*)&h2;
                } else if (EPI == 2) {
                    float2 rv = *(const float2*)(raccB + off);
                    float ox = fminf(fmaxf(0.7f * rv.x + resScale * x, -2.0f), 2.0f);
                    float oy = fminf(fmaxf(0.7f * rv.y + resScale * y, -2.0f), 2.0f);
                    *(float2*)(C + off) = make_float2(ox, oy);
                    if (mirror) {
                        ll t0 = (ll)c0 * ldC + rr;
                        ll t1 = t0 + ldC;
                        float rx = raccB[t0], ry = raccB[t1];
                        C[t0] = fminf(fmaxf(0.7f * rx + resScale * x, -2.0f), 2.0f);
                        C[t1] = fminf(fmaxf(0.7f * ry + resScale * y, -2.0f), 2.0f);
                    }
                } else {
                    *(float2*)(C + off) = make_float2(x, y);
                }
            }
        }
    }
}

// ---------------- elementwise kernels ----------------------------------------
__device__ __forceinline__ void split_bf16(float x, bf16& h, bf16& l) {
    h = __float2bfloat16(x);
    l = __float2bfloat16(x - __bfloat162float(h));
}

__global__ void conv_s_kernel(const float* __restrict__ S, const float* __restrict__ G,
                              bf16* __restrict__ Sh, bf16* __restrict__ SGh,
                              bf16* __restrict__ SGl) {
    ll i = (ll)blockIdx.x * blockDim.x + threadIdx.x;
    if (i >= (ll)BB * NN * DD) return;
    float s = S[i];
    Sh[i] = __float2bfloat16(s);
    float t = s * G[i >> 10];
    bf16 h, l; split_bf16(t, h, l);
    SGh[i] = h; SGl[i] = l;
}

__global__ void conv_w_kernel(const float* __restrict__ Win, const float* __restrict__ Wout,
                              bf16* __restrict__ Wh, bf16* __restrict__ Woh,
                              bf16* __restrict__ Wol) {
    int i = blockIdx.x * blockDim.x + threadIdx.x;
    if (i >= DD * DD) return;
    Wh[i] = __float2bfloat16(Win[i]);
    bf16 h, l; split_bf16(Wout[i], h, l);
    Woh[i] = h; Wol[i] = l;
}

// per (b,n) row: sigmoid, gates, zero diag, row-normalize -> bf16 hi/lo
__global__ __launch_bounds__(256) void coupling_kernel(
    const float* __restrict__ raccNew, const float* __restrict__ gates,
    const float* __restrict__ condPtr, bf16* __restrict__ ch, bf16* __restrict__ cl)
{
    int n = blockIdx.x, b = blockIdx.y;
    const float* row = raccNew + ((ll)b * NN + n) * NN;
    ll obase = ((ll)b * NN + n) * NN;
    float cond = fminf(fmaxf(condPtr[0], -5.0f), 5.0f);
    float gn = gates[b * NN + n];
    int t = threadIdx.x;
    float local[NN / 256];
    float sum = 0.0f;
#pragma unroll
    for (int it = 0; it < NN / 256; it++) {
        int m = t + it * 256;
        float s = 1.0f / (1.0f + expf(-cond * row[m]));
        float c = s * gates[b * NN + m] * gn;
        if (m == n) c = 0.0f;
        local[it] = c;
        sum += c;
    }
    __shared__ float red[256];
    red[t] = sum;
    __syncthreads();
    for (int s = 128; s > 0; s >>= 1) {
        if (t < s) red[t] += red[t + s];
        __syncthreads();
    }
    float inv = 1.0f / (red[0] + 1e-8f);
#pragma unroll
    for (int it = 0; it < NN / 256; it++) {
        float c = local[it] * inv;
        bf16 h, l; split_bf16(c, h, l);
        ch[obase + t + it * 256] = h;
        cl[obase + t + it * 256] = l;
    }
}

// v (b,n,d) f32 -> vT (b,d,n) bf16 hi/lo, 32x32 smem tiles
__global__ void vtrans_kernel(const float* __restrict__ v,
                              bf16* __restrict__ th, bf16* __restrict__ tl) {
    __shared__ float t[32][33];
    int b = blockIdx.z;
    int n0 = blockIdx.x * 32, d0 = blockIdx.y * 32;
    const float* vb = v + (ll)b * NN * DD;
#pragma unroll
    for (int i = 0; i < 32; i += 8)
        t[threadIdx.y + i][threadIdx.x] =
            vb[(ll)(n0 + threadIdx.y + i) * DD + d0 + threadIdx.x];
    __syncthreads();
    ll ob = (ll)b * DD * NN;
#pragma unroll
    for (int i = 0; i < 32; i += 8) {
        float val = t[threadIdx.x][threadIdx.y + i];
        ll idx = ob + (ll)(d0 + threadIdx.y + i) * NN + n0 + threadIdx.x;
        bf16 h, l; split_bf16(val, h, l);
        th[idx] = h; tl[idx] = l;
    }
}

// ---------------- launch -----------------------------------------------------
extern "C" void kernel_launch(void* const* d_in, const int* in_sizes, int n_in,
                              void* d_out, int out_size) {
    const float* S    = (const float*)d_in[0];
    const float* G    = (const float*)d_in[1];
    const float* Racc = (const float*)d_in[2];
    const float* Win  = (const float*)d_in[3];
    const float* Wout = (const float*)d_in[4];
    const float* cond = (const float*)d_in[5];

    float* field = (float*)d_out;                 // (B,N,D)
    float* raccO = field + (size_t)BB * NN * DD;  // (B,N,N)

    float *v;
    bf16 *uh, *vth, *vtl, *ch, *cl, *sh, *sgh, *sgl, *wh, *woh, *wol;
    cudaGetSymbolAddress((void**)&v, g_v);
    cudaGetSymbolAddress((void**)&uh, g_uh);
    cudaGetSymbolAddress((void**)&vth, g_vth);
    cudaGetSymbolAddress((void**)&vtl, g_vtl);
    cudaGetSymbolAddress((void**)&ch, g_ch);
    cudaGetSymbolAddress((void**)&cl, g_cl);
    cudaGetSymbolAddress((void**)&sh, g_sh);
    cudaGetSymbolAddress((void**)&sgh, g_sgh);
    cudaGetSymbolAddress((void**)&sgl, g_sgl);
    cudaGetSymbolAddress((void**)&wh, g_wh);
    cudaGetSymbolAddress((void**)&woh, g_woh);
    cudaGetSymbolAddress((void**)&wol, g_wol);

    const int SM_PLAIN = 2 * 2 * TILE_B;  // 40960
    const int SM_CORR  = 2 * 4 * TILE_B;  // 81920
    cudaFuncSetAttribute(hgemm<0, true, false>, cudaFuncAttributeMaxDynamicSharedMemorySize, SM_CORR);
    cudaFuncSetAttribute(hgemm<0, true, false>, cudaFuncAttributePreferredSharedMemoryCarveout, 100);
    cudaFuncSetAttribute(hgemm<3, false, false>, cudaFuncAttributePreferredSharedMemoryCarveout, 100);
    cudaFuncSetAttribute(hgemm<2, false, true>, cudaFuncAttributePreferredSharedMemoryCarveout, 100);

    const ll M1 = (ll)BB * NN;  // 16384

    // 0. conversions
    conv_s_kernel<<<(int)((M1 * DD + 255) / 256), 256>>>(S, G, sh, sgh, sgl);
    conv_w_kernel<<<(DD * DD + 255) / 256, 256>>>(Win, Wout, wh, woh, wol);

    // 1+2. uh = pairnorm(S @ Win^T) fused   (plain bf16, bf16 pair output)
    hgemm<3, false, false><<<dim3(DD / 128, (int)(M1 / 128), 1), 256, SM_PLAIN>>>(
        sh, nullptr, wh, nullptr, (float*)uh, DD, DD, 0, 0, 0, nullptr, 0.0f);

    // 3. raccO = clip(0.7*racc + (0.3/pairs) * U U^T, -2, 2)
    //    symmetric: only upper-tri tile pairs (16*17/2 = 136 blocks)
    hgemm<2, false, true><<<dim3(136, 1, BB), 256, SM_PLAIN>>>(
        uh, nullptr, uh, nullptr, raccO, DD, NN,
        (ll)NN * DD, (ll)NN * DD, (ll)NN * NN, Racc, 0.3f / (float)(DD / 2));

    // 4. coupling rows -> bf16 hi/lo
    coupling_kernel<<<dim3(NN, BB), 256>>>(raccO, G, cond, ch, cl);

    // 5. v = (S*g) @ Wout^T   (bf16 split corrected)
    hgemm<0, true, false><<<dim3(DD / 128, (int)(M1 / 128), 1), 256, SM_CORR>>>(
        sgh, sgl, woh, wol, v, DD, DD, 0, 0, 0, nullptr, 0.0f);

    // 5b. transpose v -> vT bf16 hi/lo
    vtrans_kernel<<<dim3(NN / 32, DD / 32, BB), dim3(32, 8)>>>(v, vth, vtl);

    // 6. field = coupling @ values   (batched, bf16 split corrected)
    hgemm<0, true, false><<<dim3(DD / 128, NN / 128, BB), 256, SM_CORR>>>(
        ch, cl, vth, vtl, field, NN, DD,
        (ll)NN * NN, (ll)DD * NN, (ll)NN * DD, nullptr, 0.0f);
}